// round 8
// baseline (speedup 1.0000x reference)
#include <cuda_runtime.h>
#include <math.h>

#define MAXB 131072
#define DIM  512
#define MAX_ITER 100

// ---------------- scratch (static __device__ — allocation-free rule) ----------------
__device__ float g_feats[MAXB * 6];
__device__ float g_h1e[MAXB * DIM];
__device__ float g_h1o[MAXB * DIM];
__device__ float g_h1b[MAXB * DIM];
__device__ unsigned g_minmax[2];   // [0]=encoded min, [1]=encoded max
__device__ unsigned g_hist[256];

// monotonic float<->uint encoding for atomic min/max
__device__ __forceinline__ unsigned fenc(float f) {
    unsigned u = __float_as_uint(f);
    return (u & 0x80000000u) ? ~u : (u | 0x80000000u);
}
__device__ __forceinline__ float fdec(unsigned e) {
    return (e & 0x80000000u) ? __uint_as_float(e ^ 0x80000000u)
                             : __uint_as_float(~e);
}

// ---------------- packed f32x2 helpers ----------------
__device__ __forceinline__ unsigned long long pack2_dup(float v) {
    unsigned long long r;
    asm("mov.b64 %0, {%1, %1};" : "=l"(r) : "f"(v));
    return r;
}
__device__ __forceinline__ void unpack2(unsigned long long v, float& lo, float& hi) {
    asm("mov.b64 {%0, %1}, %2;" : "=f"(lo), "=f"(hi) : "l"(v));
}
#define FMA2(d, a, b) asm("fma.rn.f32x2 %0, %1, %2, %0;" : "+l"(d) : "l"(a), "l"(b))

// ---------------- init ----------------
__global__ void init_kernel() {
    int t = threadIdx.x;
    if (t < 256) g_hist[t] = 0u;
    if (t == 0) { g_minmax[0] = 0xFFFFFFFFu; g_minmax[1] = 0u; }
}

// ---------------- XLA complex abs under LLVM FPOpFusion::Fast ----------------
//   mx = max(|re|,|im|); mn = min(|re|,|im|)
//   abs = (mn == 0) ? mx : mx * sqrt( fma(d, d, 1.0) ),  d = mn/mx
// (the 1 + d*d gets contracted into an fma by the backend)
__device__ __forceinline__ float xla_cabs(float re, float im) {
    float ax = fabsf(re), ay = fabsf(im);
    float mx = fmaxf(ax, ay);
    float mn = fminf(ax, ay);
    float d  = __fdiv_rn(mn, mx);
    float r  = __fmul_rn(mx, __fsqrt_rn(__fmaf_rn(d, d, 1.0f)));
    return (mn == 0.0f) ? mx : r;
}

// ---------------- mandelbrot features ----------------
// Matches XLA elemental complex-mul IR after LLVM aggressive FMA contraction:
//   re: fsub(fmul(zr,zr), fmul(zi,zi)) -> fma(zr, zr, -rn(zi*zi)); then separate fadd +x
//   im: CSE'd p = rn(zr*zi); fadd(fadd(p,p), y)  (inner fadd exact doubling)
// Escape test + magnitude use the fused scaled complex-abs above.
__global__ void mandel_kernel(const float* __restrict__ pts, int B) {
    int i = blockIdx.x * blockDim.x + threadIdx.x;
    if (i >= B) return;
    float x = pts[2 * i], y = pts[2 * i + 1];
    float zr = 0.f, zi = 0.f;
    int esc = MAX_ITER;
    bool done = false;
    for (int n = 0; n < MAX_ITER; n++) {
        if (!done) {
            float t2 = __fmul_rn(zi, zi);
            float p  = __fmul_rn(zr, zi);
            float nr = __fadd_rn(__fmaf_rn(zr, zr, -t2), x);  // fma(zr,zr,-zi^2) + x
            float ni = __fadd_rn(__fadd_rn(p, p), y);         // (2*p exact) + y
            zr = nr; zi = ni;
            if (xla_cabs(zr, zi) > 2.0f) { esc = n; done = true; }
        }
    }
    float mag = xla_cabs(zr, zi);
    g_feats[i * 6 + 0] = __fdiv_rn((float)esc, 100.0f);
    g_feats[i * 6 + 1] = mag;
    g_feats[i * 6 + 2] = zr;
    g_feats[i * 6 + 3] = zi;
    g_feats[i * 6 + 4] = x;
    g_feats[i * 6 + 5] = y;
}

// ---------------- layer-1 of escape/orbit MLPs: only 6 feature rows are nonzero ----------------
__global__ void layer1_kernel(const float* __restrict__ We1, const float* __restrict__ be1,
                              const float* __restrict__ Wo1, const float* __restrict__ bo1,
                              int B) {
    int t = blockIdx.x * blockDim.x + threadIdx.x;
    if (t >= B * DIM) return;
    int i = t >> 9;
    int j = t & (DIM - 1);
    const float* f = &g_feats[i * 6];
    float f0 = f[0], f1 = f[1], f2 = f[2], f3 = f[3], f4 = f[4], f5 = f[5];

    float se = 0.0f;
    se = fmaf(f0, We1[0 * DIM + j], se);
    se = fmaf(f1, We1[1 * DIM + j], se);
    se = fmaf(f2, We1[2 * DIM + j], se);
    se = fmaf(f3, We1[3 * DIM + j], se);
    se = fmaf(f4, We1[4 * DIM + j], se);
    se = fmaf(f5, We1[5 * DIM + j], se);
    se += be1[j];

    float so = 0.0f;
    so = fmaf(f0, Wo1[0 * DIM + j], so);
    so = fmaf(f1, Wo1[1 * DIM + j], so);
    so = fmaf(f2, Wo1[2 * DIM + j], so);
    so = fmaf(f3, Wo1[3 * DIM + j], so);
    so = fmaf(f4, Wo1[4 * DIM + j], so);
    so = fmaf(f5, Wo1[5 * DIM + j], so);
    so += bo1[j];

    g_h1e[t] = tanhf(se);
    g_h1o[t] = tanhf(so);
}

// ---------------- SGEMM: C[M,512] = act(A[M,K] @ W[K,512] + bias) ----------------
// A is given as two row-major [M,512] pieces: k<512 from A0, k>=512 from A1 (for the concat GEMM).
// BM=BN=128, BK=8, 256 threads, 8x8 microtile, f32x2 packed FMA, double-buffered smem.
#define BM 128
#define BN 128
#define BK 8

__global__ void __launch_bounds__(256)
sgemm_kernel(const float* __restrict__ A0, const float* __restrict__ A1,
             const float* __restrict__ W, const float* __restrict__ bias,
             float* __restrict__ C, int K, int act) {
    __shared__ float As[2][BK][BM];
    __shared__ float Bs[2][BK][BN];

    const int tid = threadIdx.x;
    const int m0 = blockIdx.y * BM;
    const int n0 = blockIdx.x * BN;

    // loaders
    const int arow = tid >> 1;          // 0..127
    const int acol = (tid & 1) * 4;     // 0 or 4
    const int brow = tid >> 5;          // 0..7
    const int bcol = (tid & 31) * 4;    // 0..124

    // microtile coords
    const int tr = (tid / 16) * 8;      // 0..120
    const int tc = (tid % 16) * 8;      // 0..120

    unsigned long long acc[8][4];
    #pragma unroll
    for (int i = 0; i < 8; i++)
        #pragma unroll
        for (int j = 0; j < 4; j++) acc[i][j] = 0ull;

    // preload tile 0 (k-base 0 always comes from A0)
    {
        float4 a4 = *(const float4*)(A0 + (size_t)(m0 + arow) * 512 + acol);
        As[0][acol + 0][arow] = a4.x;
        As[0][acol + 1][arow] = a4.y;
        As[0][acol + 2][arow] = a4.z;
        As[0][acol + 3][arow] = a4.w;
        float4 b4 = *(const float4*)(W + (size_t)brow * 512 + n0 + bcol);
        *(float4*)&Bs[0][brow][bcol] = b4;
    }
    __syncthreads();

    const int nT = K / BK;
    int buf = 0;
    for (int kt = 0; kt < nT; kt++) {
        float4 pa, pb;
        const bool hasNext = (kt + 1 < nT);
        if (hasNext) {
            int kb = (kt + 1) * BK;
            const float* Abase = (kb < 512) ? A0 : A1;
            int klocal = (kb < 512) ? kb : (kb - 512);
            pa = *(const float4*)(Abase + (size_t)(m0 + arow) * 512 + klocal + acol);
            pb = *(const float4*)(W + (size_t)(kb + brow) * 512 + n0 + bcol);
        }

        #pragma unroll
        for (int k = 0; k < BK; k++) {
            float4 aLo = *(const float4*)&As[buf][k][tr];
            float4 aHi = *(const float4*)&As[buf][k][tr + 4];
            unsigned long long b2[4];
            #pragma unroll
            for (int j = 0; j < 4; j++)
                b2[j] = *(const unsigned long long*)&Bs[buf][k][tc + 2 * j];
            float av[8] = {aLo.x, aLo.y, aLo.z, aLo.w, aHi.x, aHi.y, aHi.z, aHi.w};
            #pragma unroll
            for (int i = 0; i < 8; i++) {
                unsigned long long a2 = pack2_dup(av[i]);
                #pragma unroll
                for (int j = 0; j < 4; j++) FMA2(acc[i][j], a2, b2[j]);
            }
        }

        if (hasNext) {
            int nb = buf ^ 1;
            As[nb][acol + 0][arow] = pa.x;
            As[nb][acol + 1][arow] = pa.y;
            As[nb][acol + 2][arow] = pa.z;
            As[nb][acol + 3][arow] = pa.w;
            *(float4*)&Bs[nb][brow][bcol] = pb;
            __syncthreads();
            buf = nb;
        }
    }

    // epilogue
    float bv[8];
    #pragma unroll
    for (int u = 0; u < 8; u++) bv[u] = bias[n0 + tc + u];

    #pragma unroll
    for (int i = 0; i < 8; i++) {
        float o[8];
        #pragma unroll
        for (int j = 0; j < 4; j++) unpack2(acc[i][j], o[2 * j], o[2 * j + 1]);
        #pragma unroll
        for (int u = 0; u < 8; u++) o[u] += bv[u];
        if (act) {
            #pragma unroll
            for (int u = 0; u < 8; u++) o[u] = tanhf(o[u]);
        }
        float* cp = C + (size_t)(m0 + tr + i) * 512 + n0 + tc;
        *(float4*)(cp + 0) = make_float4(o[0], o[1], o[2], o[3]);
        *(float4*)(cp + 4) = make_float4(o[4], o[5], o[6], o[7]);
    }
}

// ---------------- row stats: is_in_set, fractal_dimension, boundary min/max ----------------
__global__ void rowstats_kernel(const float* __restrict__ escf,
                                const float* __restrict__ bndf,
                                float* __restrict__ iso,
                                float* __restrict__ frac) {
    int warp = threadIdx.x >> 5, lane = threadIdx.x & 31;
    int row = blockIdx.x * 8 + warp;

    // escape mean
    const float4* e4 = (const float4*)(escf + (size_t)row * DIM);
    float s = 0.f;
    #pragma unroll
    for (int p = 0; p < 4; p++) {
        float4 v = e4[lane + p * 32];
        s += v.x + v.y + v.z + v.w;
    }
    #pragma unroll
    for (int o = 16; o; o >>= 1) s += __shfl_xor_sync(0xffffffffu, s, o);
    if (lane == 0) iso[row] = (s * (1.0f / 512.0f) > 0.5f) ? 1.0f : 0.0f;

    // boundary mean + min/max
    const float4* b4 = (const float4*)(bndf + (size_t)row * DIM);
    float sb = 0.f, mn = 3.4e38f, mx = -3.4e38f;
    #pragma unroll
    for (int p = 0; p < 4; p++) {
        float4 v = b4[lane + p * 32];
        sb += v.x + v.y + v.z + v.w;
        mn = fminf(mn, fminf(fminf(v.x, v.y), fminf(v.z, v.w)));
        mx = fmaxf(mx, fmaxf(fmaxf(v.x, v.y), fmaxf(v.z, v.w)));
    }
    #pragma unroll
    for (int o = 16; o; o >>= 1) {
        sb += __shfl_xor_sync(0xffffffffu, sb, o);
        mn = fminf(mn, __shfl_xor_sync(0xffffffffu, mn, o));
        mx = fmaxf(mx, __shfl_xor_sync(0xffffffffu, mx, o));
    }
    if (lane == 0) {
        float m = sb * (1.0f / 512.0f);
        frac[row] = 1.0f / (1.0f + expf(-m));
    }

    __shared__ float smn[8], smx[8];
    if (lane == 0) { smn[warp] = mn; smx[warp] = mx; }
    __syncthreads();
    if (threadIdx.x == 0) {
        float bmn = smn[0], bmx = smx[0];
        #pragma unroll
        for (int w = 1; w < 8; w++) { bmn = fminf(bmn, smn[w]); bmx = fmaxf(bmx, smx[w]); }
        atomicMin(&g_minmax[0], fenc(bmn));
        atomicMax(&g_minmax[1], fenc(bmx));
    }
}

// ---------------- histogram of boundary field ----------------
// 32 lane-private sub-histograms in smem: slot = bin*32+lane -> bank == lane, conflict-free.
__global__ void hist_kernel(const float* __restrict__ bnd, int n4) {
    __shared__ unsigned sh[256 * 32];
    for (int t = threadIdx.x; t < 256 * 32; t += blockDim.x) sh[t] = 0u;
    __syncthreads();

    float mn = fdec(g_minmax[0]);
    float mx = fdec(g_minmax[1]);
    float scale = 256.0f / (mx - mn);
    int lane = threadIdx.x & 31;

    const float4* p = (const float4*)bnd;
    for (int idx = blockIdx.x * blockDim.x + threadIdx.x; idx < n4;
         idx += gridDim.x * blockDim.x) {
        float4 v = p[idx];
        int b0 = min(255, max(0, (int)((v.x - mn) * scale)));
        int b1 = min(255, max(0, (int)((v.y - mn) * scale)));
        int b2 = min(255, max(0, (int)((v.z - mn) * scale)));
        int b3 = min(255, max(0, (int)((v.w - mn) * scale)));
        atomicAdd(&sh[b0 * 32 + lane], 1u);
        atomicAdd(&sh[b1 * 32 + lane], 1u);
        atomicAdd(&sh[b2 * 32 + lane], 1u);
        atomicAdd(&sh[b3 * 32 + lane], 1u);
    }
    __syncthreads();
    for (int t = threadIdx.x; t < 256; t += blockDim.x) {
        unsigned sum = 0;
        #pragma unroll
        for (int l = 0; l < 32; l++) sum += sh[t * 32 + l];
        if (sum) atomicAdd(&g_hist[t], sum);
    }
}

// ---------------- entropy scalar ----------------
__global__ void finalize_kernel(float* __restrict__ comp, float total) {
    __shared__ float sh[256];
    int t = threadIdx.x;
    float p = (float)g_hist[t] / total;
    sh[t] = p * log2f(p + 1e-10f);
    __syncthreads();
    for (int s = 128; s; s >>= 1) {
        if (t < s) sh[t] += sh[t + s];
        __syncthreads();
    }
    if (t == 0) comp[0] = -sh[0];
}

// ---------------- launch ----------------
extern "C" void kernel_launch(void* const* d_in, const int* in_sizes, int n_in,
                              void* d_out, int out_size) {
    const float* pts = (const float*)d_in[0];
    const float* We1 = (const float*)d_in[1];
    const float* be1 = (const float*)d_in[2];
    const float* We2 = (const float*)d_in[3];
    const float* be2 = (const float*)d_in[4];
    const float* Wo1 = (const float*)d_in[5];
    const float* bo1 = (const float*)d_in[6];
    const float* Wo2 = (const float*)d_in[7];
    const float* bo2 = (const float*)d_in[8];
    const float* Wb1 = (const float*)d_in[9];
    const float* bb1 = (const float*)d_in[10];
    const float* Wb2 = (const float*)d_in[11];
    const float* bb2 = (const float*)d_in[12];

    const int B = in_sizes[0] / 2;

    float* out  = (float*)d_out;
    float* out0 = out;                              // escape_field  [B,512]
    float* out1 = out0 + (size_t)B * DIM;           // orbit_field   [B,512]
    float* out2 = out1 + (size_t)B * DIM;           // boundary_field[B,512]
    float* iso  = out2 + (size_t)B * DIM;           // is_in_set [B]
    float* frac = iso + B;                          // fractal_dimension [B]
    float* comp = frac + B;                         // complexity [1]

    static float* p_h1e = nullptr;
    static float* p_h1o = nullptr;
    static float* p_h1b = nullptr;
    if (!p_h1e) {
        cudaGetSymbolAddress((void**)&p_h1e, g_h1e);
        cudaGetSymbolAddress((void**)&p_h1o, g_h1o);
        cudaGetSymbolAddress((void**)&p_h1b, g_h1b);
    }

    init_kernel<<<1, 256>>>();
    mandel_kernel<<<(B + 255) / 256, 256>>>(pts, B);
    layer1_kernel<<<(B * DIM) / 256, 256>>>(We1, be1, Wo1, bo1, B);

    dim3 gg(DIM / BN, B / BM);
    // escape_field = h1e @ We2 + be2
    sgemm_kernel<<<gg, 256>>>(p_h1e, p_h1e, We2, be2, out0, 512, 0);
    // orbit_field = h1o @ Wo2 + bo2
    sgemm_kernel<<<gg, 256>>>(p_h1o, p_h1o, Wo2, bo2, out1, 512, 0);
    // h1b = tanh([escape|orbit] @ Wb1 + bb1)   (K = 1024 split across out0/out1)
    sgemm_kernel<<<gg, 256>>>(out0, out1, Wb1, bb1, p_h1b, 1024, 1);
    // boundary_field = h1b @ Wb2 + bb2
    sgemm_kernel<<<gg, 256>>>(p_h1b, p_h1b, Wb2, bb2, out2, 512, 0);

    rowstats_kernel<<<B / 8, 256>>>(out0, out2, iso, frac);
    hist_kernel<<<1024, 256>>>(out2, (B * DIM) / 4);
    finalize_kernel<<<1, 256>>>(comp, (float)((size_t)B * DIM));
}

// round 9
// speedup vs baseline: 1.5213x; 1.5213x over previous
#include <cuda_runtime.h>
#include <math.h>

#define MAXB 131072
#define DIM  512
#define MAX_ITER 100

// ---------------- scratch (static __device__ — allocation-free rule) ----------------
__device__ float g_feats[MAXB * 6];
__device__ float g_h1e[MAXB * DIM];
__device__ float g_h1o[MAXB * DIM];
__device__ float g_h1b[MAXB * DIM];
__device__ unsigned g_minmax[2];   // [0]=encoded min, [1]=encoded max
__device__ unsigned g_hist[256];

// monotonic float<->uint encoding for atomic min/max
__device__ __forceinline__ unsigned fenc(float f) {
    unsigned u = __float_as_uint(f);
    return (u & 0x80000000u) ? ~u : (u | 0x80000000u);
}
__device__ __forceinline__ float fdec(unsigned e) {
    return (e & 0x80000000u) ? __uint_as_float(e ^ 0x80000000u)
                             : __uint_as_float(~e);
}

// ---------------- packed f32x2 helpers ----------------
__device__ __forceinline__ unsigned long long pack2_dup(float v) {
    unsigned long long r;
    asm("mov.b64 %0, {%1, %1};" : "=l"(r) : "f"(v));
    return r;
}
__device__ __forceinline__ void unpack2(unsigned long long v, float& lo, float& hi) {
    asm("mov.b64 {%0, %1}, %2;" : "=f"(lo), "=f"(hi) : "l"(v));
}
#define FMA2(d, a, b) asm("fma.rn.f32x2 %0, %1, %2, %0;" : "+l"(d) : "l"(a), "l"(b))

// ---------------- init ----------------
__global__ void init_kernel() {
    int t = threadIdx.x;
    if (t < 256) g_hist[t] = 0u;
    if (t == 0) { g_minmax[0] = 0xFFFFFFFFu; g_minmax[1] = 0u; }
}

// ---------------- XLA complex abs under LLVM FPOpFusion::Fast ----------------
// CONFIRMED CORRECT in R8 (rel_err 7e-7) — do not modify.
__device__ __forceinline__ float xla_cabs(float re, float im) {
    float ax = fabsf(re), ay = fabsf(im);
    float mx = fmaxf(ax, ay);
    float mn = fminf(ax, ay);
    float d  = __fdiv_rn(mn, mx);
    float r  = __fmul_rn(mx, __fsqrt_rn(__fmaf_rn(d, d, 1.0f)));
    return (mn == 0.0f) ? mx : r;
}

// ---------------- mandelbrot features ----------------
// CONFIRMED CORRECT in R8 (rel_err 7e-7) — matches XLA elemental IR after LLVM
// aggressive FMA contraction. Do not modify the arithmetic.
__global__ void mandel_kernel(const float* __restrict__ pts, int B) {
    int i = blockIdx.x * blockDim.x + threadIdx.x;
    if (i >= B) return;
    float x = pts[2 * i], y = pts[2 * i + 1];
    float zr = 0.f, zi = 0.f;
    int esc = MAX_ITER;
    bool done = false;
    for (int n = 0; n < MAX_ITER; n++) {
        if (!done) {
            float t2 = __fmul_rn(zi, zi);
            float p  = __fmul_rn(zr, zi);
            float nr = __fadd_rn(__fmaf_rn(zr, zr, -t2), x);  // fma(zr,zr,-zi^2) + x
            float ni = __fadd_rn(__fadd_rn(p, p), y);         // (2*p exact) + y
            zr = nr; zi = ni;
            if (xla_cabs(zr, zi) > 2.0f) { esc = n; done = true; }
        }
    }
    float mag = xla_cabs(zr, zi);
    g_feats[i * 6 + 0] = __fdiv_rn((float)esc, 100.0f);
    g_feats[i * 6 + 1] = mag;
    g_feats[i * 6 + 2] = zr;
    g_feats[i * 6 + 3] = zi;
    g_feats[i * 6 + 4] = x;
    g_feats[i * 6 + 5] = y;
}

// ---------------- layer-1 of escape/orbit MLPs: only 6 feature rows are nonzero ----------------
__global__ void layer1_kernel(const float* __restrict__ We1, const float* __restrict__ be1,
                              const float* __restrict__ Wo1, const float* __restrict__ bo1,
                              int B) {
    int t = blockIdx.x * blockDim.x + threadIdx.x;
    if (t >= B * DIM) return;
    int i = t >> 9;
    int j = t & (DIM - 1);
    const float* f = &g_feats[i * 6];
    float f0 = f[0], f1 = f[1], f2 = f[2], f3 = f[3], f4 = f[4], f5 = f[5];

    float se = 0.0f;
    se = fmaf(f0, We1[0 * DIM + j], se);
    se = fmaf(f1, We1[1 * DIM + j], se);
    se = fmaf(f2, We1[2 * DIM + j], se);
    se = fmaf(f3, We1[3 * DIM + j], se);
    se = fmaf(f4, We1[4 * DIM + j], se);
    se = fmaf(f5, We1[5 * DIM + j], se);
    se += be1[j];

    float so = 0.0f;
    so = fmaf(f0, Wo1[0 * DIM + j], so);
    so = fmaf(f1, Wo1[1 * DIM + j], so);
    so = fmaf(f2, Wo1[2 * DIM + j], so);
    so = fmaf(f3, Wo1[3 * DIM + j], so);
    so = fmaf(f4, Wo1[4 * DIM + j], so);
    so = fmaf(f5, Wo1[5 * DIM + j], so);
    so += bo1[j];

    g_h1e[t] = tanhf(se);
    g_h1o[t] = tanhf(so);
}

// ---------------- SGEMM: C[M,512] = act(A[M,K] @ W[K,512] + bias) ----------------
// A is given as two row-major [M,512] pieces: k<512 from A0, k>=512 from A1 (for the concat GEMM).
// BM=BN=128, BK=8, 256 threads, 8x8 microtile, f32x2 packed FMA, double-buffered smem.
// __launch_bounds__(256, 2): R8 measured regs=130 -> 1 CTA/SM -> occ 12.4%, fma 38.9%.
// Capping at 128 regs fits 2 CTAs/SM (4 warps/SMSP) to fill barrier/LDS latency holes.
#define BM 128
#define BN 128
#define BK 8

__global__ void __launch_bounds__(256, 2)
sgemm_kernel(const float* __restrict__ A0, const float* __restrict__ A1,
             const float* __restrict__ W, const float* __restrict__ bias,
             float* __restrict__ C, int K, int act) {
    __shared__ float As[2][BK][BM];
    __shared__ float Bs[2][BK][BN];

    const int tid = threadIdx.x;
    const int m0 = blockIdx.y * BM;
    const int n0 = blockIdx.x * BN;

    // loaders
    const int arow = tid >> 1;          // 0..127
    const int acol = (tid & 1) * 4;     // 0 or 4
    const int brow = tid >> 5;          // 0..7
    const int bcol = (tid & 31) * 4;    // 0..124

    // microtile coords
    const int tr = (tid / 16) * 8;      // 0..120
    const int tc = (tid % 16) * 8;      // 0..120

    unsigned long long acc[8][4];
    #pragma unroll
    for (int i = 0; i < 8; i++)
        #pragma unroll
        for (int j = 0; j < 4; j++) acc[i][j] = 0ull;

    // preload tile 0 (k-base 0 always comes from A0)
    {
        float4 a4 = *(const float4*)(A0 + (size_t)(m0 + arow) * 512 + acol);
        As[0][acol + 0][arow] = a4.x;
        As[0][acol + 1][arow] = a4.y;
        As[0][acol + 2][arow] = a4.z;
        As[0][acol + 3][arow] = a4.w;
        float4 b4 = *(const float4*)(W + (size_t)brow * 512 + n0 + bcol);
        *(float4*)&Bs[0][brow][bcol] = b4;
    }
    __syncthreads();

    const int nT = K / BK;
    int buf = 0;
    for (int kt = 0; kt < nT; kt++) {
        float4 pa, pb;
        const bool hasNext = (kt + 1 < nT);
        if (hasNext) {
            int kb = (kt + 1) * BK;
            const float* Abase = (kb < 512) ? A0 : A1;
            int klocal = (kb < 512) ? kb : (kb - 512);
            pa = *(const float4*)(Abase + (size_t)(m0 + arow) * 512 + klocal + acol);
            pb = *(const float4*)(W + (size_t)(kb + brow) * 512 + n0 + bcol);
        }

        #pragma unroll
        for (int k = 0; k < BK; k++) {
            float4 aLo = *(const float4*)&As[buf][k][tr];
            float4 aHi = *(const float4*)&As[buf][k][tr + 4];
            unsigned long long b2[4];
            #pragma unroll
            for (int j = 0; j < 4; j++)
                b2[j] = *(const unsigned long long*)&Bs[buf][k][tc + 2 * j];
            float av[8] = {aLo.x, aLo.y, aLo.z, aLo.w, aHi.x, aHi.y, aHi.z, aHi.w};
            #pragma unroll
            for (int i = 0; i < 8; i++) {
                unsigned long long a2 = pack2_dup(av[i]);
                #pragma unroll
                for (int j = 0; j < 4; j++) FMA2(acc[i][j], a2, b2[j]);
            }
        }

        if (hasNext) {
            int nb = buf ^ 1;
            As[nb][acol + 0][arow] = pa.x;
            As[nb][acol + 1][arow] = pa.y;
            As[nb][acol + 2][arow] = pa.z;
            As[nb][acol + 3][arow] = pa.w;
            *(float4*)&Bs[nb][brow][bcol] = pb;
            __syncthreads();
            buf = nb;
        }
    }

    // epilogue
    float bv[8];
    #pragma unroll
    for (int u = 0; u < 8; u++) bv[u] = bias[n0 + tc + u];

    #pragma unroll
    for (int i = 0; i < 8; i++) {
        float o[8];
        #pragma unroll
        for (int j = 0; j < 4; j++) unpack2(acc[i][j], o[2 * j], o[2 * j + 1]);
        #pragma unroll
        for (int u = 0; u < 8; u++) o[u] += bv[u];
        if (act) {
            #pragma unroll
            for (int u = 0; u < 8; u++) o[u] = tanhf(o[u]);
        }
        float* cp = C + (size_t)(m0 + tr + i) * 512 + n0 + tc;
        *(float4*)(cp + 0) = make_float4(o[0], o[1], o[2], o[3]);
        *(float4*)(cp + 4) = make_float4(o[4], o[5], o[6], o[7]);
    }
}

// ---------------- row stats: is_in_set, fractal_dimension, boundary min/max ----------------
__global__ void rowstats_kernel(const float* __restrict__ escf,
                                const float* __restrict__ bndf,
                                float* __restrict__ iso,
                                float* __restrict__ frac) {
    int warp = threadIdx.x >> 5, lane = threadIdx.x & 31;
    int row = blockIdx.x * 8 + warp;

    // escape mean
    const float4* e4 = (const float4*)(escf + (size_t)row * DIM);
    float s = 0.f;
    #pragma unroll
    for (int p = 0; p < 4; p++) {
        float4 v = e4[lane + p * 32];
        s += v.x + v.y + v.z + v.w;
    }
    #pragma unroll
    for (int o = 16; o; o >>= 1) s += __shfl_xor_sync(0xffffffffu, s, o);
    if (lane == 0) iso[row] = (s * (1.0f / 512.0f) > 0.5f) ? 1.0f : 0.0f;

    // boundary mean + min/max
    const float4* b4 = (const float4*)(bndf + (size_t)row * DIM);
    float sb = 0.f, mn = 3.4e38f, mx = -3.4e38f;
    #pragma unroll
    for (int p = 0; p < 4; p++) {
        float4 v = b4[lane + p * 32];
        sb += v.x + v.y + v.z + v.w;
        mn = fminf(mn, fminf(fminf(v.x, v.y), fminf(v.z, v.w)));
        mx = fmaxf(mx, fmaxf(fmaxf(v.x, v.y), fmaxf(v.z, v.w)));
    }
    #pragma unroll
    for (int o = 16; o; o >>= 1) {
        sb += __shfl_xor_sync(0xffffffffu, sb, o);
        mn = fminf(mn, __shfl_xor_sync(0xffffffffu, mn, o));
        mx = fmaxf(mx, __shfl_xor_sync(0xffffffffu, mx, o));
    }
    if (lane == 0) {
        float m = sb * (1.0f / 512.0f);
        frac[row] = 1.0f / (1.0f + expf(-m));
    }

    __shared__ float smn[8], smx[8];
    if (lane == 0) { smn[warp] = mn; smx[warp] = mx; }
    __syncthreads();
    if (threadIdx.x == 0) {
        float bmn = smn[0], bmx = smx[0];
        #pragma unroll
        for (int w = 1; w < 8; w++) { bmn = fminf(bmn, smn[w]); bmx = fmaxf(bmx, smx[w]); }
        atomicMin(&g_minmax[0], fenc(bmn));
        atomicMax(&g_minmax[1], fenc(bmx));
    }
}

// ---------------- histogram of boundary field ----------------
// 32 lane-private sub-histograms in smem: slot = bin*32+lane -> bank == lane, conflict-free.
__global__ void hist_kernel(const float* __restrict__ bnd, int n4) {
    __shared__ unsigned sh[256 * 32];
    for (int t = threadIdx.x; t < 256 * 32; t += blockDim.x) sh[t] = 0u;
    __syncthreads();

    float mn = fdec(g_minmax[0]);
    float mx = fdec(g_minmax[1]);
    float scale = 256.0f / (mx - mn);
    int lane = threadIdx.x & 31;

    const float4* p = (const float4*)bnd;
    for (int idx = blockIdx.x * blockDim.x + threadIdx.x; idx < n4;
         idx += gridDim.x * blockDim.x) {
        float4 v = p[idx];
        int b0 = min(255, max(0, (int)((v.x - mn) * scale)));
        int b1 = min(255, max(0, (int)((v.y - mn) * scale)));
        int b2 = min(255, max(0, (int)((v.z - mn) * scale)));
        int b3 = min(255, max(0, (int)((v.w - mn) * scale)));
        atomicAdd(&sh[b0 * 32 + lane], 1u);
        atomicAdd(&sh[b1 * 32 + lane], 1u);
        atomicAdd(&sh[b2 * 32 + lane], 1u);
        atomicAdd(&sh[b3 * 32 + lane], 1u);
    }
    __syncthreads();
    for (int t = threadIdx.x; t < 256; t += blockDim.x) {
        unsigned sum = 0;
        #pragma unroll
        for (int l = 0; l < 32; l++) sum += sh[t * 32 + l];
        if (sum) atomicAdd(&g_hist[t], sum);
    }
}

// ---------------- entropy scalar ----------------
__global__ void finalize_kernel(float* __restrict__ comp, float total) {
    __shared__ float sh[256];
    int t = threadIdx.x;
    float p = (float)g_hist[t] / total;
    sh[t] = p * log2f(p + 1e-10f);
    __syncthreads();
    for (int s = 128; s; s >>= 1) {
        if (t < s) sh[t] += sh[t + s];
        __syncthreads();
    }
    if (t == 0) comp[0] = -sh[0];
}

// ---------------- launch ----------------
extern "C" void kernel_launch(void* const* d_in, const int* in_sizes, int n_in,
                              void* d_out, int out_size) {
    const float* pts = (const float*)d_in[0];
    const float* We1 = (const float*)d_in[1];
    const float* be1 = (const float*)d_in[2];
    const float* We2 = (const float*)d_in[3];
    const float* be2 = (const float*)d_in[4];
    const float* Wo1 = (const float*)d_in[5];
    const float* bo1 = (const float*)d_in[6];
    const float* Wo2 = (const float*)d_in[7];
    const float* bo2 = (const float*)d_in[8];
    const float* Wb1 = (const float*)d_in[9];
    const float* bb1 = (const float*)d_in[10];
    const float* Wb2 = (const float*)d_in[11];
    const float* bb2 = (const float*)d_in[12];

    const int B = in_sizes[0] / 2;

    float* out  = (float*)d_out;
    float* out0 = out;                              // escape_field  [B,512]
    float* out1 = out0 + (size_t)B * DIM;           // orbit_field   [B,512]
    float* out2 = out1 + (size_t)B * DIM;           // boundary_field[B,512]
    float* iso  = out2 + (size_t)B * DIM;           // is_in_set [B]
    float* frac = iso + B;                          // fractal_dimension [B]
    float* comp = frac + B;                         // complexity [1]

    static float* p_h1e = nullptr;
    static float* p_h1o = nullptr;
    static float* p_h1b = nullptr;
    if (!p_h1e) {
        cudaGetSymbolAddress((void**)&p_h1e, g_h1e);
        cudaGetSymbolAddress((void**)&p_h1o, g_h1o);
        cudaGetSymbolAddress((void**)&p_h1b, g_h1b);
    }

    init_kernel<<<1, 256>>>();
    mandel_kernel<<<(B + 255) / 256, 256>>>(pts, B);
    layer1_kernel<<<(B * DIM) / 256, 256>>>(We1, be1, Wo1, bo1, B);

    dim3 gg(DIM / BN, B / BM);
    // escape_field = h1e @ We2 + be2
    sgemm_kernel<<<gg, 256>>>(p_h1e, p_h1e, We2, be2, out0, 512, 0);
    // orbit_field = h1o @ Wo2 + bo2
    sgemm_kernel<<<gg, 256>>>(p_h1o, p_h1o, Wo2, bo2, out1, 512, 0);
    // h1b = tanh([escape|orbit] @ Wb1 + bb1)   (K = 1024 split across out0/out1)
    sgemm_kernel<<<gg, 256>>>(out0, out1, Wb1, bb1, p_h1b, 1024, 1);
    // boundary_field = h1b @ Wb2 + bb2
    sgemm_kernel<<<gg, 256>>>(p_h1b, p_h1b, Wb2, bb2, out2, 512, 0);

    rowstats_kernel<<<B / 8, 256>>>(out0, out2, iso, frac);
    hist_kernel<<<1024, 256>>>(out2, (B * DIM) / 4);
    finalize_kernel<<<1, 256>>>(comp, (float)((size_t)B * DIM));
}

// round 12
// speedup vs baseline: 3.3210x; 2.1830x over previous
#include <cuda_runtime.h>
#include <cuda_bf16.h>
#include <math.h>
#include <stdint.h>

#define MAXB 131072
#define DIM  512
#define MAX_ITER 100

// ---------------- scratch (static __device__ — allocation-free rule) ----------------
__device__ float g_feats[MAXB * 6];
// bf16 hi/lo split operands for tensor-core GEMMs
__device__ __nv_bfloat16 g_h1e_h[MAXB * DIM], g_h1e_l[MAXB * DIM];
__device__ __nv_bfloat16 g_h1o_h[MAXB * DIM], g_h1o_l[MAXB * DIM];
__device__ __nv_bfloat16 g_o0_h[MAXB * DIM],  g_o0_l[MAXB * DIM];
__device__ __nv_bfloat16 g_o1_h[MAXB * DIM],  g_o1_l[MAXB * DIM];
__device__ __nv_bfloat16 g_hb_h[MAXB * DIM],  g_hb_l[MAXB * DIM];
__device__ __nv_bfloat16 g_W_h[1024 * DIM],   g_W_l[1024 * DIM];
__device__ unsigned g_minmax[2];
__device__ unsigned g_hist[256];

// ---------------- small helpers ----------------
__device__ __forceinline__ unsigned fenc(float f) {
    unsigned u = __float_as_uint(f);
    return (u & 0x80000000u) ? ~u : (u | 0x80000000u);
}
__device__ __forceinline__ float fdec(unsigned e) {
    return (e & 0x80000000u) ? __uint_as_float(e ^ 0x80000000u)
                             : __uint_as_float(~e);
}
__device__ __forceinline__ void f2bf2(float f, __nv_bfloat16& h, __nv_bfloat16& l) {
    h = __float2bfloat16_rn(f);
    l = __float2bfloat16_rn(f - __bfloat162float(h));
}
__device__ __forceinline__ uint32_t smem_to_u32(const void* p) {
    uint32_t a;
    asm("{ .reg .u64 t; cvta.to.shared.u64 t, %1; cvt.u32.u64 %0, t; }" : "=r"(a) : "l"(p));
    return a;
}

// ---------------- non-'a' tensor-core primitives (sm_80-era, valid at compute_103) ----------------
#define LDSM_X4(r, addr) \
    asm volatile("ldmatrix.sync.aligned.m8n8.x4.shared.b16 {%0,%1,%2,%3}, [%4];" \
        : "=r"((r)[0]), "=r"((r)[1]), "=r"((r)[2]), "=r"((r)[3]) : "r"(addr))
#define LDSM_X2(r, addr) \
    asm volatile("ldmatrix.sync.aligned.m8n8.x2.shared.b16 {%0,%1}, [%2];" \
        : "=r"((r)[0]), "=r"((r)[1]) : "r"(addr))
#define MMA16816(c, a, b) \
    asm volatile("mma.sync.aligned.m16n8k16.row.col.f32.bf16.bf16.f32 " \
        "{%0,%1,%2,%3}, {%4,%5,%6,%7}, {%8,%9}, {%0,%1,%2,%3};" \
        : "+f"((c)[0]), "+f"((c)[1]), "+f"((c)[2]), "+f"((c)[3]) \
        : "r"((a)[0]), "r"((a)[1]), "r"((a)[2]), "r"((a)[3]), "r"((b)[0]), "r"((b)[1]))
#define CP_ASYNC16(dst, src) \
    asm volatile("cp.async.cg.shared.global [%0], [%1], 16;" :: "r"(dst), "l"(src))
#define CP_COMMIT() asm volatile("cp.async.commit_group;" ::: "memory")
#define CP_WAIT0()  asm volatile("cp.async.wait_group 0;" ::: "memory")

// ---------------- init ----------------
__global__ void init_kernel() {
    int t = threadIdx.x;
    if (t < 256) g_hist[t] = 0u;
    if (t == 0) { g_minmax[0] = 0xFFFFFFFFu; g_minmax[1] = 0u; }
}

// ---------------- mandelbrot features (CONFIRMED bit-exact in R8 — DO NOT MODIFY) ----------------
__device__ __forceinline__ float xla_cabs(float re, float im) {
    float ax = fabsf(re), ay = fabsf(im);
    float mx = fmaxf(ax, ay);
    float mn = fminf(ax, ay);
    float d  = __fdiv_rn(mn, mx);
    float r  = __fmul_rn(mx, __fsqrt_rn(__fmaf_rn(d, d, 1.0f)));
    return (mn == 0.0f) ? mx : r;
}
__global__ void mandel_kernel(const float* __restrict__ pts, int B) {
    int i = blockIdx.x * blockDim.x + threadIdx.x;
    if (i >= B) return;
    float x = pts[2 * i], y = pts[2 * i + 1];
    float zr = 0.f, zi = 0.f;
    int esc = MAX_ITER;
    bool done = false;
    for (int n = 0; n < MAX_ITER; n++) {
        if (!done) {
            float t2 = __fmul_rn(zi, zi);
            float p  = __fmul_rn(zr, zi);
            float nr = __fadd_rn(__fmaf_rn(zr, zr, -t2), x);
            float ni = __fadd_rn(__fadd_rn(p, p), y);
            zr = nr; zi = ni;
            if (xla_cabs(zr, zi) > 2.0f) { esc = n; done = true; }
        }
    }
    float mag = xla_cabs(zr, zi);
    g_feats[i * 6 + 0] = __fdiv_rn((float)esc, 100.0f);
    g_feats[i * 6 + 1] = mag;
    g_feats[i * 6 + 2] = zr;
    g_feats[i * 6 + 3] = zi;
    g_feats[i * 6 + 4] = x;
    g_feats[i * 6 + 5] = y;
}

// ---------------- layer-1: 6 nonzero features; writes bf16 hi/lo split ----------------
__global__ void layer1_kernel(const float* __restrict__ We1, const float* __restrict__ be1,
                              const float* __restrict__ Wo1, const float* __restrict__ bo1,
                              int B) {
    int t = blockIdx.x * blockDim.x + threadIdx.x;
    if (t >= B * DIM) return;
    int i = t >> 9;
    int j = t & (DIM - 1);
    const float* f = &g_feats[i * 6];
    float f0 = f[0], f1 = f[1], f2 = f[2], f3 = f[3], f4 = f[4], f5 = f[5];

    float se = 0.0f;
    se = fmaf(f0, We1[0 * DIM + j], se);
    se = fmaf(f1, We1[1 * DIM + j], se);
    se = fmaf(f2, We1[2 * DIM + j], se);
    se = fmaf(f3, We1[3 * DIM + j], se);
    se = fmaf(f4, We1[4 * DIM + j], se);
    se = fmaf(f5, We1[5 * DIM + j], se);
    se += be1[j];

    float so = 0.0f;
    so = fmaf(f0, Wo1[0 * DIM + j], so);
    so = fmaf(f1, Wo1[1 * DIM + j], so);
    so = fmaf(f2, Wo1[2 * DIM + j], so);
    so = fmaf(f3, Wo1[3 * DIM + j], so);
    so = fmaf(f4, Wo1[4 * DIM + j], so);
    so = fmaf(f5, Wo1[5 * DIM + j], so);
    so += bo1[j];

    __nv_bfloat16 h, l;
    f2bf2(tanhf(se), h, l); g_h1e_h[t] = h; g_h1e_l[t] = l;
    f2bf2(tanhf(so), h, l); g_h1o_h[t] = h; g_h1o_l[t] = l;
}

// ---------------- W split prep ----------------
__global__ void prepw_kernel(const float* __restrict__ W,
                             __nv_bfloat16* __restrict__ Wh,
                             __nv_bfloat16* __restrict__ Wl, int n) {
    int i = blockIdx.x * blockDim.x + threadIdx.x;
    if (i >= n) return;
    __nv_bfloat16 h, l;
    f2bf2(W[i], h, l);
    Wh[i] = h; Wl[i] = l;
}

// ---------------- bf16x3 GEMM via mma.sync (HMMA) ----------------
// C[128,128] tile per CTA; K-chunks of 32; C = Ah*Wh + Ah*Wl + Al*Wh in fp32.
// smem per stage: A_h, A_l: 128 rows x 32k, 80B row stride (64B data + 16B pad);
//                 W_h, W_l: 128 n-rows x 32k, same stride (transposed on load).
#define STG  40960
#define A_HO 0
#define A_LO 10240
#define W_HO 20480
#define W_LO 30720
#define TG_SMEM (2 * STG)

__global__ void __launch_bounds__(256, 2)
tgemm_kernel(const __nv_bfloat16* __restrict__ Ah0, const __nv_bfloat16* __restrict__ Al0,
             const __nv_bfloat16* __restrict__ Ah1, const __nv_bfloat16* __restrict__ Al1,
             const __nv_bfloat16* __restrict__ Wh,  const __nv_bfloat16* __restrict__ Wl,
             const float* __restrict__ bias,
             float* __restrict__ Cf,
             __nv_bfloat16* __restrict__ Ch, __nv_bfloat16* __restrict__ Cl,
             int K, int act) {
    extern __shared__ char sm[];
    const uint32_t sb = smem_to_u32(sm);
    const int tid  = threadIdx.x;
    const int wid  = tid >> 5;
    const int lane = tid & 31;
    const int m0 = blockIdx.y * 128;
    const int n0 = blockIdx.x * 128;

    const int wm = (wid & 1) * 64;      // warp M offset (2 warps)
    const int wn = (wid >> 1) * 32;     // warp N offset (4 warps)

    // ldmatrix per-lane base offsets
    const int q  = lane >> 3, lr = lane & 7;
    const uint32_t a_off = (uint32_t)((wm + (q & 1) * 8 + lr) * 80 + (q >> 1) * 16);
    const uint32_t b_off = (uint32_t)((wn + lr) * 80 + ((lane >> 3) & 1) * 16);

    // loader coords
    const int arow = tid >> 2;          // 0..63 (x2 iters -> 128 rows? no: idx below)
    const int n2 = (tid & 63) * 2;      // W: even n row
    const int kg = tid >> 6;            // W: k-group 0..3 (8 k each)

    float acc[4][4][4];
    #pragma unroll
    for (int i = 0; i < 4; i++)
        #pragma unroll
        for (int j = 0; j < 4; j++)
            #pragma unroll
            for (int e = 0; e < 4; e++) acc[i][j][e] = 0.0f;

    const int nC = K / 32;

    // ---- A cp.async loader: chunk kbn into stage st ----
    auto loadA = [&](int kbn, int st) {
        const __nv_bfloat16* ah = (kbn < 512) ? Ah0 : Ah1;
        const __nv_bfloat16* al = (kbn < 512) ? Al0 : Al1;
        const int ko = (kbn < 512) ? kbn : (kbn - 512);
        #pragma unroll
        for (int i = 0; i < 2; i++) {
            int idx = tid + 256 * i;
            int row = idx >> 2, p = idx & 3;
            uint32_t dh = sb + st * STG + A_HO + row * 80 + p * 16;
            uint32_t dl = sb + st * STG + A_LO + row * 80 + p * 16;
            const __nv_bfloat16* gh = ah + (size_t)(m0 + row) * 512 + ko + p * 8;
            const __nv_bfloat16* gl = al + (size_t)(m0 + row) * 512 + ko + p * 8;
            CP_ASYNC16(dh, gh);
            CP_ASYNC16(dl, gl);
        }
        CP_COMMIT();
    };
    // ---- W LDG (transpose source regs) ----
    uint32_t vh[8], vl[8];
    auto loadW = [&](int kbn) {
        #pragma unroll
        for (int j = 0; j < 8; j++) {
            size_t wo = (size_t)(kbn + kg * 8 + j) * 512 + n0 + n2;
            vh[j] = *(const uint32_t*)(Wh + wo);
            vl[j] = *(const uint32_t*)(Wl + wo);
        }
    };
    auto storeW = [&](int st) {
        uint32_t h0[4], h1[4], l0[4], l1[4];
        #pragma unroll
        for (int p = 0; p < 4; p++) {
            h0[p] = (vh[2 * p] & 0xFFFFu) | (vh[2 * p + 1] << 16);
            h1[p] = (vh[2 * p] >> 16)     | (vh[2 * p + 1] & 0xFFFF0000u);
            l0[p] = (vl[2 * p] & 0xFFFFu) | (vl[2 * p + 1] << 16);
            l1[p] = (vl[2 * p] >> 16)     | (vl[2 * p + 1] & 0xFFFF0000u);
        }
        char* wb = sm + st * STG;
        uint32_t s0 = (uint32_t)(n2 * 80 + kg * 16);
        uint32_t s1 = (uint32_t)((n2 + 1) * 80 + kg * 16);
        *(uint4*)(wb + W_HO + s0) = make_uint4(h0[0], h0[1], h0[2], h0[3]);
        *(uint4*)(wb + W_HO + s1) = make_uint4(h1[0], h1[1], h1[2], h1[3]);
        *(uint4*)(wb + W_LO + s0) = make_uint4(l0[0], l0[1], l0[2], l0[3]);
        *(uint4*)(wb + W_LO + s1) = make_uint4(l1[0], l1[1], l1[2], l1[3]);
    };

    // ---- prologue: chunk 0 into stage 0 ----
    loadW(0);
    loadA(0, 0);
    CP_WAIT0();
    storeW(0);
    __syncthreads();

    for (int c = 0; c < nC; c++) {
        const int s = c & 1;
        const bool hasNext = (c + 1 < nC);
        if (hasNext) {
            loadW((c + 1) * 32);
            loadA((c + 1) * 32, s ^ 1);
        }

        // ---- mma on stage s ----
        const uint32_t AH = sb + s * STG + A_HO;
        const uint32_t AL = sb + s * STG + A_LO;
        const uint32_t WHs = sb + s * STG + W_HO;
        const uint32_t WLs = sb + s * STG + W_LO;
        #pragma unroll
        for (int ks = 0; ks < 2; ks++) {
            const uint32_t kb2 = ks * 32;   // 16 k * 2B
            uint32_t af[4][4], bh[4][2], bl[4][2];
            #pragma unroll
            for (int mt = 0; mt < 4; mt++) LDSM_X4(af[mt], AH + a_off + mt * 1280 + kb2);
            #pragma unroll
            for (int nt = 0; nt < 4; nt++) LDSM_X2(bh[nt], WHs + b_off + nt * 640 + kb2);
            #pragma unroll
            for (int mt = 0; mt < 4; mt++)
                #pragma unroll
                for (int nt = 0; nt < 4; nt++) MMA16816(acc[mt][nt], af[mt], bh[nt]);
            #pragma unroll
            for (int nt = 0; nt < 4; nt++) LDSM_X2(bl[nt], WLs + b_off + nt * 640 + kb2);
            #pragma unroll
            for (int mt = 0; mt < 4; mt++)
                #pragma unroll
                for (int nt = 0; nt < 4; nt++) MMA16816(acc[mt][nt], af[mt], bl[nt]);
            #pragma unroll
            for (int mt = 0; mt < 4; mt++) LDSM_X4(af[mt], AL + a_off + mt * 1280 + kb2);
            #pragma unroll
            for (int mt = 0; mt < 4; mt++)
                #pragma unroll
                for (int nt = 0; nt < 4; nt++) MMA16816(acc[mt][nt], af[mt], bh[nt]);
        }

        if (hasNext) {
            CP_WAIT0();
            storeW(s ^ 1);
        }
        __syncthreads();
    }

    // ---- epilogue ----
    #pragma unroll
    for (int nt = 0; nt < 4; nt++) {
        const int cb = n0 + wn + nt * 8 + (lane & 3) * 2;
        const float b0v = __ldg(bias + cb);
        const float b1v = __ldg(bias + cb + 1);
        #pragma unroll
        for (int mt = 0; mt < 4; mt++) {
            const int r0 = m0 + wm + mt * 16 + (lane >> 2);
            const int r1 = r0 + 8;
            float v00 = acc[mt][nt][0] + b0v;
            float v01 = acc[mt][nt][1] + b1v;
            float v10 = acc[mt][nt][2] + b0v;
            float v11 = acc[mt][nt][3] + b1v;
            if (act) { v00 = tanhf(v00); v01 = tanhf(v01); v10 = tanhf(v10); v11 = tanhf(v11); }
            if (Cf) {
                *(float2*)(Cf + (size_t)r0 * 512 + cb) = make_float2(v00, v01);
                *(float2*)(Cf + (size_t)r1 * 512 + cb) = make_float2(v10, v11);
            }
            if (Ch) {
                __nv_bfloat16 h00, l00, h01, l01, h10, l10, h11, l11;
                f2bf2(v00, h00, l00); f2bf2(v01, h01, l01);
                f2bf2(v10, h10, l10); f2bf2(v11, h11, l11);
                uint32_t ph0 = (uint32_t)__bfloat16_as_ushort(h00) | ((uint32_t)__bfloat16_as_ushort(h01) << 16);
                uint32_t pl0 = (uint32_t)__bfloat16_as_ushort(l00) | ((uint32_t)__bfloat16_as_ushort(l01) << 16);
                uint32_t ph1 = (uint32_t)__bfloat16_as_ushort(h10) | ((uint32_t)__bfloat16_as_ushort(h11) << 16);
                uint32_t pl1 = (uint32_t)__bfloat16_as_ushort(l10) | ((uint32_t)__bfloat16_as_ushort(l11) << 16);
                *(uint32_t*)(Ch + (size_t)r0 * 512 + cb) = ph0;
                *(uint32_t*)(Cl + (size_t)r0 * 512 + cb) = pl0;
                *(uint32_t*)(Ch + (size_t)r1 * 512 + cb) = ph1;
                *(uint32_t*)(Cl + (size_t)r1 * 512 + cb) = pl1;
            }
        }
    }
}

// ---------------- row stats ----------------
__global__ void rowstats_kernel(const float* __restrict__ escf,
                                const float* __restrict__ bndf,
                                float* __restrict__ iso,
                                float* __restrict__ frac) {
    int warp = threadIdx.x >> 5, lane = threadIdx.x & 31;
    int row = blockIdx.x * 8 + warp;

    const float4* e4 = (const float4*)(escf + (size_t)row * DIM);
    float s = 0.f;
    #pragma unroll
    for (int p = 0; p < 4; p++) {
        float4 v = e4[lane + p * 32];
        s += v.x + v.y + v.z + v.w;
    }
    #pragma unroll
    for (int o = 16; o; o >>= 1) s += __shfl_xor_sync(0xffffffffu, s, o);
    if (lane == 0) iso[row] = (s * (1.0f / 512.0f) > 0.5f) ? 1.0f : 0.0f;

    const float4* b4 = (const float4*)(bndf + (size_t)row * DIM);
    float sb = 0.f, mn = 3.4e38f, mx = -3.4e38f;
    #pragma unroll
    for (int p = 0; p < 4; p++) {
        float4 v = b4[lane + p * 32];
        sb += v.x + v.y + v.z + v.w;
        mn = fminf(mn, fminf(fminf(v.x, v.y), fminf(v.z, v.w)));
        mx = fmaxf(mx, fmaxf(fmaxf(v.x, v.y), fmaxf(v.z, v.w)));
    }
    #pragma unroll
    for (int o = 16; o; o >>= 1) {
        sb += __shfl_xor_sync(0xffffffffu, sb, o);
        mn = fminf(mn, __shfl_xor_sync(0xffffffffu, mn, o));
        mx = fmaxf(mx, __shfl_xor_sync(0xffffffffu, mx, o));
    }
    if (lane == 0) {
        float m = sb * (1.0f / 512.0f);
        frac[row] = 1.0f / (1.0f + expf(-m));
    }

    __shared__ float smn[8], smx[8];
    if (lane == 0) { smn[warp] = mn; smx[warp] = mx; }
    __syncthreads();
    if (threadIdx.x == 0) {
        float bmn = smn[0], bmx = smx[0];
        #pragma unroll
        for (int w = 1; w < 8; w++) { bmn = fminf(bmn, smn[w]); bmx = fmaxf(bmx, smx[w]); }
        atomicMin(&g_minmax[0], fenc(bmn));
        atomicMax(&g_minmax[1], fenc(bmx));
    }
}

// ---------------- histogram ----------------
__global__ void hist_kernel(const float* __restrict__ bnd, int n4) {
    __shared__ unsigned sh[256 * 32];
    for (int t = threadIdx.x; t < 256 * 32; t += blockDim.x) sh[t] = 0u;
    __syncthreads();

    float mn = fdec(g_minmax[0]);
    float mx = fdec(g_minmax[1]);
    float scale = 256.0f / (mx - mn);
    int lane = threadIdx.x & 31;

    const float4* p = (const float4*)bnd;
    for (int idx = blockIdx.x * blockDim.x + threadIdx.x; idx < n4;
         idx += gridDim.x * blockDim.x) {
        float4 v = p[idx];
        int b0 = min(255, max(0, (int)((v.x - mn) * scale)));
        int b1 = min(255, max(0, (int)((v.y - mn) * scale)));
        int b2 = min(255, max(0, (int)((v.z - mn) * scale)));
        int b3 = min(255, max(0, (int)((v.w - mn) * scale)));
        atomicAdd(&sh[b0 * 32 + lane], 1u);
        atomicAdd(&sh[b1 * 32 + lane], 1u);
        atomicAdd(&sh[b2 * 32 + lane], 1u);
        atomicAdd(&sh[b3 * 32 + lane], 1u);
    }
    __syncthreads();
    for (int t = threadIdx.x; t < 256; t += blockDim.x) {
        unsigned sum = 0;
        #pragma unroll
        for (int l = 0; l < 32; l++) sum += sh[t * 32 + l];
        if (sum) atomicAdd(&g_hist[t], sum);
    }
}

// ---------------- entropy ----------------
__global__ void finalize_kernel(float* __restrict__ comp, float total) {
    __shared__ float sh[256];
    int t = threadIdx.x;
    float p = (float)g_hist[t] / total;
    sh[t] = p * log2f(p + 1e-10f);
    __syncthreads();
    for (int s = 128; s; s >>= 1) {
        if (t < s) sh[t] += sh[t + s];
        __syncthreads();
    }
    if (t == 0) comp[0] = -sh[0];
}

// ---------------- launch ----------------
extern "C" void kernel_launch(void* const* d_in, const int* in_sizes, int n_in,
                              void* d_out, int out_size) {
    const float* pts = (const float*)d_in[0];
    const float* We1 = (const float*)d_in[1];
    const float* be1 = (const float*)d_in[2];
    const float* We2 = (const float*)d_in[3];
    const float* be2 = (const float*)d_in[4];
    const float* Wo1 = (const float*)d_in[5];
    const float* bo1 = (const float*)d_in[6];
    const float* Wo2 = (const float*)d_in[7];
    const float* bo2 = (const float*)d_in[8];
    const float* Wb1 = (const float*)d_in[9];
    const float* bb1 = (const float*)d_in[10];
    const float* Wb2 = (const float*)d_in[11];
    const float* bb2 = (const float*)d_in[12];

    const int B = in_sizes[0] / 2;

    float* out  = (float*)d_out;
    float* out0 = out;
    float* out1 = out0 + (size_t)B * DIM;
    float* out2 = out1 + (size_t)B * DIM;
    float* iso  = out2 + (size_t)B * DIM;
    float* frac = iso + B;
    float* comp = frac + B;

    static __nv_bfloat16 *peh=nullptr,*pel,*poh,*pol,*p0h,*p0l,*p1h,*p1l,*pbh,*pbl,*pWh,*pWl;
    if (!peh) {
        cudaGetSymbolAddress((void**)&peh, g_h1e_h);
        cudaGetSymbolAddress((void**)&pel, g_h1e_l);
        cudaGetSymbolAddress((void**)&poh, g_h1o_h);
        cudaGetSymbolAddress((void**)&pol, g_h1o_l);
        cudaGetSymbolAddress((void**)&p0h, g_o0_h);
        cudaGetSymbolAddress((void**)&p0l, g_o0_l);
        cudaGetSymbolAddress((void**)&p1h, g_o1_h);
        cudaGetSymbolAddress((void**)&p1l, g_o1_l);
        cudaGetSymbolAddress((void**)&pbh, g_hb_h);
        cudaGetSymbolAddress((void**)&pbl, g_hb_l);
        cudaGetSymbolAddress((void**)&pWh, g_W_h);
        cudaGetSymbolAddress((void**)&pWl, g_W_l);
        cudaFuncSetAttribute(tgemm_kernel, cudaFuncAttributeMaxDynamicSharedMemorySize, TG_SMEM);
    }

    init_kernel<<<1, 256>>>();
    mandel_kernel<<<(B + 255) / 256, 256>>>(pts, B);
    layer1_kernel<<<(B * DIM) / 256, 256>>>(We1, be1, Wo1, bo1, B);

    dim3 gg(4, B / 128);
    // escape_field = h1e @ We2 + be2  (fp32 out + bf16 split for gemm3)
    prepw_kernel<<<(512 * 512) / 256, 256>>>(We2, pWh, pWl, 512 * 512);
    tgemm_kernel<<<gg, 256, TG_SMEM>>>(peh, pel, peh, pel, pWh, pWl, be2,
                                       out0, p0h, p0l, 512, 0);
    // orbit_field = h1o @ Wo2 + bo2
    prepw_kernel<<<(512 * 512) / 256, 256>>>(Wo2, pWh, pWl, 512 * 512);
    tgemm_kernel<<<gg, 256, TG_SMEM>>>(poh, pol, poh, pol, pWh, pWl, bo2,
                                       out1, p1h, p1l, 512, 0);
    // h1b = tanh([escape|orbit] @ Wb1 + bb1)  (K=1024, bf16 out only)
    prepw_kernel<<<(1024 * 512) / 256, 256>>>(Wb1, pWh, pWl, 1024 * 512);
    tgemm_kernel<<<gg, 256, TG_SMEM>>>(p0h, p0l, p1h, p1l, pWh, pWl, bb1,
                                       nullptr, pbh, pbl, 1024, 1);
    // boundary_field = h1b @ Wb2 + bb2  (fp32 out only)
    prepw_kernel<<<(512 * 512) / 256, 256>>>(Wb2, pWh, pWl, 512 * 512);
    tgemm_kernel<<<gg, 256, TG_SMEM>>>(pbh, pbl, pbh, pbl, pWh, pWl, bb2,
                                       out2, nullptr, nullptr, 512, 0);

    rowstats_kernel<<<B / 8, 256>>>(out0, out2, iso, frac);
    hist_kernel<<<1024, 256>>>(out2, (B * DIM) / 4);
    finalize_kernel<<<1, 256>>>(comp, (float)((size_t)B * DIM));
}

// round 14
// speedup vs baseline: 3.3718x; 1.0153x over previous
#include <cuda_runtime.h>
#include <cuda_bf16.h>
#include <math.h>
#include <stdint.h>

#define MAXB 131072
#define DIM  512
#define MAX_ITER 100

// ---------------- scratch (static __device__ — allocation-free rule) ----------------
__device__ float g_feats[MAXB * 6];
__device__ __nv_bfloat16 g_h1e_h[MAXB * DIM], g_h1e_l[MAXB * DIM];
__device__ __nv_bfloat16 g_h1o_h[MAXB * DIM], g_h1o_l[MAXB * DIM];
__device__ __nv_bfloat16 g_hb_h[MAXB * DIM],  g_hb_l[MAXB * DIM];
// pre-split weights (all four GEMMs, prepared upfront)
__device__ __nv_bfloat16 g_W0h[512 * DIM],  g_W0l[512 * DIM];    // We2
__device__ __nv_bfloat16 g_W1h[512 * DIM],  g_W1l[512 * DIM];    // Wo2
__device__ __nv_bfloat16 g_W2h[1024 * DIM], g_W2l[1024 * DIM];   // Wb1
__device__ __nv_bfloat16 g_W3h[512 * DIM],  g_W3l[512 * DIM];    // Wb2
__device__ float g_rs_esc[MAXB];   // escape_field row sums
__device__ float g_rs_bnd[MAXB];   // boundary_field row sums
__device__ unsigned g_minmax[2];
__device__ unsigned g_hist[256];

// ---------------- small helpers ----------------
__device__ __forceinline__ unsigned fenc(float f) {
    unsigned u = __float_as_uint(f);
    return (u & 0x80000000u) ? ~u : (u | 0x80000000u);
}
__device__ __forceinline__ float fdec(unsigned e) {
    return (e & 0x80000000u) ? __uint_as_float(e ^ 0x80000000u)
                             : __uint_as_float(~e);
}
__device__ __forceinline__ void f2bf2(float f, __nv_bfloat16& h, __nv_bfloat16& l) {
    h = __float2bfloat16_rn(f);
    l = __float2bfloat16_rn(f - __bfloat162float(h));
}
__device__ __forceinline__ uint32_t smem_to_u32(const void* p) {
    uint32_t a;
    asm("{ .reg .u64 t; cvta.to.shared.u64 t, %1; cvt.u32.u64 %0, t; }" : "=r"(a) : "l"(p));
    return a;
}

// ---------------- non-'a' tensor-core primitives (compute_103-safe) ----------------
#define LDSM_X4(r, addr) \
    asm volatile("ldmatrix.sync.aligned.m8n8.x4.shared.b16 {%0,%1,%2,%3}, [%4];" \
        : "=r"((r)[0]), "=r"((r)[1]), "=r"((r)[2]), "=r"((r)[3]) : "r"(addr))
#define LDSM_X2(r, addr) \
    asm volatile("ldmatrix.sync.aligned.m8n8.x2.shared.b16 {%0,%1}, [%2];" \
        : "=r"((r)[0]), "=r"((r)[1]) : "r"(addr))
#define MMA16816(c, a, b) \
    asm volatile("mma.sync.aligned.m16n8k16.row.col.f32.bf16.bf16.f32 " \
        "{%0,%1,%2,%3}, {%4,%5,%6,%7}, {%8,%9}, {%0,%1,%2,%3};" \
        : "+f"((c)[0]), "+f"((c)[1]), "+f"((c)[2]), "+f"((c)[3]) \
        : "r"((a)[0]), "r"((a)[1]), "r"((a)[2]), "r"((a)[3]), "r"((b)[0]), "r"((b)[1]))
#define CP_ASYNC16(dst, src) \
    asm volatile("cp.async.cg.shared.global [%0], [%1], 16;" :: "r"(dst), "l"(src))
#define CP_COMMIT() asm volatile("cp.async.commit_group;" ::: "memory")
#define CP_WAIT0()  asm volatile("cp.async.wait_group 0;" ::: "memory")

// ---------------- init: zero hist/minmax/rowsums ----------------
__global__ void init_kernel() {
    int t = blockIdx.x * 256 + threadIdx.x;
    if (t < MAXB) { g_rs_esc[t] = 0.0f; g_rs_bnd[t] = 0.0f; }
    if (blockIdx.x == 0) {
        if (threadIdx.x < 256) g_hist[threadIdx.x] = 0u;
        if (threadIdx.x == 0) { g_minmax[0] = 0xFFFFFFFFu; g_minmax[1] = 0u; }
    }
}

// ---------------- mandelbrot features (CONFIRMED bit-exact in R8 — DO NOT MODIFY) ----------------
__device__ __forceinline__ float xla_cabs(float re, float im) {
    float ax = fabsf(re), ay = fabsf(im);
    float mx = fmaxf(ax, ay);
    float mn = fminf(ax, ay);
    float d  = __fdiv_rn(mn, mx);
    float r  = __fmul_rn(mx, __fsqrt_rn(__fmaf_rn(d, d, 1.0f)));
    return (mn == 0.0f) ? mx : r;
}
__global__ void mandel_kernel(const float* __restrict__ pts, int B) {
    int i = blockIdx.x * blockDim.x + threadIdx.x;
    if (i >= B) return;
    float x = pts[2 * i], y = pts[2 * i + 1];
    float zr = 0.f, zi = 0.f;
    int esc = MAX_ITER;
    bool done = false;
    for (int n = 0; n < MAX_ITER; n++) {
        if (!done) {
            float t2 = __fmul_rn(zi, zi);
            float p  = __fmul_rn(zr, zi);
            float nr = __fadd_rn(__fmaf_rn(zr, zr, -t2), x);
            float ni = __fadd_rn(__fadd_rn(p, p), y);
            zr = nr; zi = ni;
            if (xla_cabs(zr, zi) > 2.0f) { esc = n; done = true; }
        }
    }
    float mag = xla_cabs(zr, zi);
    g_feats[i * 6 + 0] = __fdiv_rn((float)esc, 100.0f);
    g_feats[i * 6 + 1] = mag;
    g_feats[i * 6 + 2] = zr;
    g_feats[i * 6 + 3] = zi;
    g_feats[i * 6 + 4] = x;
    g_feats[i * 6 + 5] = y;
}

// ---------------- layer-1: 6 nonzero features; writes bf16 hi/lo split ----------------
__global__ void layer1_kernel(const float* __restrict__ We1, const float* __restrict__ be1,
                              const float* __restrict__ Wo1, const float* __restrict__ bo1,
                              int B) {
    int t = blockIdx.x * blockDim.x + threadIdx.x;
    if (t >= B * DIM) return;
    int i = t >> 9;
    int j = t & (DIM - 1);
    const float* f = &g_feats[i * 6];
    float f0 = f[0], f1 = f[1], f2 = f[2], f3 = f[3], f4 = f[4], f5 = f[5];

    float se = 0.0f;
    se = fmaf(f0, We1[0 * DIM + j], se);
    se = fmaf(f1, We1[1 * DIM + j], se);
    se = fmaf(f2, We1[2 * DIM + j], se);
    se = fmaf(f3, We1[3 * DIM + j], se);
    se = fmaf(f4, We1[4 * DIM + j], se);
    se = fmaf(f5, We1[5 * DIM + j], se);
    se += be1[j];

    float so = 0.0f;
    so = fmaf(f0, Wo1[0 * DIM + j], so);
    so = fmaf(f1, Wo1[1 * DIM + j], so);
    so = fmaf(f2, Wo1[2 * DIM + j], so);
    so = fmaf(f3, Wo1[3 * DIM + j], so);
    so = fmaf(f4, Wo1[4 * DIM + j], so);
    so = fmaf(f5, Wo1[5 * DIM + j], so);
    so += bo1[j];

    __nv_bfloat16 h, l;
    f2bf2(tanhf(se), h, l); g_h1e_h[t] = h; g_h1e_l[t] = l;
    f2bf2(tanhf(so), h, l); g_h1o_h[t] = h; g_h1o_l[t] = l;
}

// ---------------- all-weights split prep (single launch) ----------------
__global__ void prepw_all_kernel(const float* __restrict__ We2, const float* __restrict__ Wo2,
                                 const float* __restrict__ Wb1, const float* __restrict__ Wb2) {
    int i = blockIdx.x * blockDim.x + threadIdx.x;   // 0 .. 1310719
    const float* src; __nv_bfloat16 *dh, *dl; int off;
    if (i < 262144)       { src = We2; off = i;           dh = g_W0h; dl = g_W0l; }
    else if (i < 524288)  { src = Wo2; off = i - 262144;  dh = g_W1h; dl = g_W1l; }
    else if (i < 1048576) { src = Wb1; off = i - 524288;  dh = g_W2h; dl = g_W2l; }
    else                  { src = Wb2; off = i - 1048576; dh = g_W3h; dl = g_W3l; }
    __nv_bfloat16 h, l;
    f2bf2(src[off], h, l);
    dh[off] = h; dl[off] = l;
}

// ---------------- bf16x3 GEMM via mma.sync (HMMA) ----------------
// C[128,128] tile per CTA; K-chunks of 32; C = Ah*Wh + Ah*Wl + Al*Wh in fp32.
// A source: either pre-split bf16 pairs (cp.async) or fp32 (LDG + split in loader).
#define STG  40960
#define A_HO 0
#define A_LO 10240
#define W_HO 20480
#define W_LO 30720
#define TG_SMEM (2 * STG)

__global__ void __launch_bounds__(256, 2)
tgemm_kernel(const __nv_bfloat16* __restrict__ Ah0, const __nv_bfloat16* __restrict__ Al0,
             const __nv_bfloat16* __restrict__ Ah1, const __nv_bfloat16* __restrict__ Al1,
             const float* __restrict__ Af0, const float* __restrict__ Af1, int aIsF32,
             const __nv_bfloat16* __restrict__ Wh,  const __nv_bfloat16* __restrict__ Wl,
             const float* __restrict__ bias,
             float* __restrict__ Cf,
             __nv_bfloat16* __restrict__ Ch, __nv_bfloat16* __restrict__ Cl,
             float* __restrict__ rowsum, int doMinMax,
             int K, int act) {
    extern __shared__ char sm[];
    __shared__ float s_mn[8], s_mx[8];
    const uint32_t sb = smem_to_u32(sm);
    const int tid  = threadIdx.x;
    const int wid  = tid >> 5;
    const int lane = tid & 31;
    const int m0 = blockIdx.y * 128;
    const int n0 = blockIdx.x * 128;

    const int wm = (wid & 1) * 64;
    const int wn = (wid >> 1) * 32;

    const int q  = lane >> 3, lr = lane & 7;
    const uint32_t a_off = (uint32_t)((wm + (q & 1) * 8 + lr) * 80 + (q >> 1) * 16);
    const uint32_t b_off = (uint32_t)((wn + lr) * 80 + ((lane >> 3) & 1) * 16);

    const int n2 = (tid & 63) * 2;
    const int kg = tid >> 6;

    float acc[4][4][4];
    #pragma unroll
    for (int i = 0; i < 4; i++)
        #pragma unroll
        for (int j = 0; j < 4; j++)
            #pragma unroll
            for (int e = 0; e < 4; e++) acc[i][j][e] = 0.0f;

    const int nC = K / 32;

    // ---- A loaders ----
    float fA[16];   // fp32-A staging (2 slots x 8 floats)
    auto issueA = [&](int kbn, int st) {
        if (!aIsF32) {
            const __nv_bfloat16* ah = (kbn < 512) ? Ah0 : Ah1;
            const __nv_bfloat16* al = (kbn < 512) ? Al0 : Al1;
            const int ko = (kbn < 512) ? kbn : (kbn - 512);
            #pragma unroll
            for (int i = 0; i < 2; i++) {
                int idx = tid + 256 * i;
                int row = idx >> 2, p = idx & 3;
                uint32_t dh = sb + st * STG + A_HO + row * 80 + p * 16;
                uint32_t dl = sb + st * STG + A_LO + row * 80 + p * 16;
                const __nv_bfloat16* gh = ah + (size_t)(m0 + row) * 512 + ko + p * 8;
                const __nv_bfloat16* gl = al + (size_t)(m0 + row) * 512 + ko + p * 8;
                CP_ASYNC16(dh, gh);
                CP_ASYNC16(dl, gl);
            }
            CP_COMMIT();
        } else {
            const float* a = (kbn < 512) ? Af0 : Af1;
            const int ko = (kbn < 512) ? kbn : (kbn - 512);
            #pragma unroll
            for (int i = 0; i < 2; i++) {
                int idx = tid + 256 * i;
                int row = idx >> 2, p = idx & 3;
                const float4* g = (const float4*)(a + (size_t)(m0 + row) * 512 + ko + p * 8);
                float4 x = g[0], y = g[1];
                fA[i * 8 + 0] = x.x; fA[i * 8 + 1] = x.y; fA[i * 8 + 2] = x.z; fA[i * 8 + 3] = x.w;
                fA[i * 8 + 4] = y.x; fA[i * 8 + 5] = y.y; fA[i * 8 + 6] = y.z; fA[i * 8 + 7] = y.w;
            }
        }
    };
    auto storeA = [&](int st) {   // fp32 path only: convert + STS
        #pragma unroll
        for (int i = 0; i < 2; i++) {
            int idx = tid + 256 * i;
            int row = idx >> 2, p = idx & 3;
            uint32_t ph[4], pl[4];
            #pragma unroll
            for (int j = 0; j < 4; j++) {
                __nv_bfloat16 h0, l0, h1, l1;
                f2bf2(fA[i * 8 + 2 * j],     h0, l0);
                f2bf2(fA[i * 8 + 2 * j + 1], h1, l1);
                ph[j] = (uint32_t)__bfloat16_as_ushort(h0) | ((uint32_t)__bfloat16_as_ushort(h1) << 16);
                pl[j] = (uint32_t)__bfloat16_as_ushort(l0) | ((uint32_t)__bfloat16_as_ushort(l1) << 16);
            }
            char* base = sm + st * STG;
            *(uint4*)(base + A_HO + row * 80 + p * 16) = make_uint4(ph[0], ph[1], ph[2], ph[3]);
            *(uint4*)(base + A_LO + row * 80 + p * 16) = make_uint4(pl[0], pl[1], pl[2], pl[3]);
        }
    };
    // ---- W loaders ----
    uint32_t vh[8], vl[8];
    auto loadW = [&](int kbn) {
        #pragma unroll
        for (int j = 0; j < 8; j++) {
            size_t wo = (size_t)(kbn + kg * 8 + j) * 512 + n0 + n2;
            vh[j] = *(const uint32_t*)(Wh + wo);
            vl[j] = *(const uint32_t*)(Wl + wo);
        }
    };
    auto storeW = [&](int st) {
        uint32_t h0[4], h1[4], l0[4], l1[4];
        #pragma unroll
        for (int p = 0; p < 4; p++) {
            h0[p] = (vh[2 * p] & 0xFFFFu) | (vh[2 * p + 1] << 16);
            h1[p] = (vh[2 * p] >> 16)     | (vh[2 * p + 1] & 0xFFFF0000u);
            l0[p] = (vl[2 * p] & 0xFFFFu) | (vl[2 * p + 1] << 16);
            l1[p] = (vl[2 * p] >> 16)     | (vl[2 * p + 1] & 0xFFFF0000u);
        }
        char* wb = sm + st * STG;
        uint32_t s0 = (uint32_t)(n2 * 80 + kg * 16);
        uint32_t s1 = (uint32_t)((n2 + 1) * 80 + kg * 16);
        *(uint4*)(wb + W_HO + s0) = make_uint4(h0[0], h0[1], h0[2], h0[3]);
        *(uint4*)(wb + W_HO + s1) = make_uint4(h1[0], h1[1], h1[2], h1[3]);
        *(uint4*)(wb + W_LO + s0) = make_uint4(l0[0], l0[1], l0[2], l0[3]);
        *(uint4*)(wb + W_LO + s1) = make_uint4(l1[0], l1[1], l1[2], l1[3]);
    };

    // ---- prologue ----
    loadW(0);
    issueA(0, 0);
    if (!aIsF32) CP_WAIT0();
    storeW(0);
    if (aIsF32) storeA(0);
    __syncthreads();

    for (int c = 0; c < nC; c++) {
        const int s = c & 1;
        const bool hasNext = (c + 1 < nC);
        if (hasNext) {
            loadW((c + 1) * 32);
            issueA((c + 1) * 32, s ^ 1);
        }

        const uint32_t AH = sb + s * STG + A_HO;
        const uint32_t AL = sb + s * STG + A_LO;
        const uint32_t WHs = sb + s * STG + W_HO;
        const uint32_t WLs = sb + s * STG + W_LO;
        #pragma unroll
        for (int ks = 0; ks < 2; ks++) {
            const uint32_t kb2 = ks * 32;
            uint32_t af[4][4], bh[4][2], bl[4][2];
            #pragma unroll
            for (int mt = 0; mt < 4; mt++) LDSM_X4(af[mt], AH + a_off + mt * 1280 + kb2);
            #pragma unroll
            for (int nt = 0; nt < 4; nt++) LDSM_X2(bh[nt], WHs + b_off + nt * 640 + kb2);
            #pragma unroll
            for (int mt = 0; mt < 4; mt++)
                #pragma unroll
                for (int nt = 0; nt < 4; nt++) MMA16816(acc[mt][nt], af[mt], bh[nt]);
            #pragma unroll
            for (int nt = 0; nt < 4; nt++) LDSM_X2(bl[nt], WLs + b_off + nt * 640 + kb2);
            #pragma unroll
            for (int mt = 0; mt < 4; mt++)
                #pragma unroll
                for (int nt = 0; nt < 4; nt++) MMA16816(acc[mt][nt], af[mt], bl[nt]);
            #pragma unroll
            for (int mt = 0; mt < 4; mt++) LDSM_X4(af[mt], AL + a_off + mt * 1280 + kb2);
            #pragma unroll
            for (int mt = 0; mt < 4; mt++)
                #pragma unroll
                for (int nt = 0; nt < 4; nt++) MMA16816(acc[mt][nt], af[mt], bh[nt]);
        }

        if (hasNext) {
            if (!aIsF32) CP_WAIT0();
            storeW(s ^ 1);
            if (aIsF32) storeA(s ^ 1);
        }
        __syncthreads();
    }

    // ---- epilogue ----
    float rsum0[4] = {0, 0, 0, 0}, rsum1[4] = {0, 0, 0, 0};
    float vmn = 3.4e38f, vmx = -3.4e38f;

    #pragma unroll
    for (int nt = 0; nt < 4; nt++) {
        const int cb = n0 + wn + nt * 8 + (lane & 3) * 2;
        const float b0v = __ldg(bias + cb);
        const float b1v = __ldg(bias + cb + 1);
        #pragma unroll
        for (int mt = 0; mt < 4; mt++) {
            const int r0 = m0 + wm + mt * 16 + (lane >> 2);
            const int r1 = r0 + 8;
            float v00 = acc[mt][nt][0] + b0v;
            float v01 = acc[mt][nt][1] + b1v;
            float v10 = acc[mt][nt][2] + b0v;
            float v11 = acc[mt][nt][3] + b1v;
            if (act) { v00 = tanhf(v00); v01 = tanhf(v01); v10 = tanhf(v10); v11 = tanhf(v11); }
            if (rowsum) {
                rsum0[mt] += v00 + v01;
                rsum1[mt] += v10 + v11;
            }
            if (doMinMax) {
                vmn = fminf(vmn, fminf(fminf(v00, v01), fminf(v10, v11)));
                vmx = fmaxf(vmx, fmaxf(fmaxf(v00, v01), fmaxf(v10, v11)));
            }
            if (Cf) {
                *(float2*)(Cf + (size_t)r0 * 512 + cb) = make_float2(v00, v01);
                *(float2*)(Cf + (size_t)r1 * 512 + cb) = make_float2(v10, v11);
            }
            if (Ch) {
                __nv_bfloat16 h00, l00, h01, l01, h10, l10, h11, l11;
                f2bf2(v00, h00, l00); f2bf2(v01, h01, l01);
                f2bf2(v10, h10, l10); f2bf2(v11, h11, l11);
                uint32_t ph0 = (uint32_t)__bfloat16_as_ushort(h00) | ((uint32_t)__bfloat16_as_ushort(h01) << 16);
                uint32_t pl0 = (uint32_t)__bfloat16_as_ushort(l00) | ((uint32_t)__bfloat16_as_ushort(l01) << 16);
                uint32_t ph1 = (uint32_t)__bfloat16_as_ushort(h10) | ((uint32_t)__bfloat16_as_ushort(h11) << 16);
                uint32_t pl1 = (uint32_t)__bfloat16_as_ushort(l10) | ((uint32_t)__bfloat16_as_ushort(l11) << 16);
                *(uint32_t*)(Ch + (size_t)r0 * 512 + cb) = ph0;
                *(uint32_t*)(Cl + (size_t)r0 * 512 + cb) = pl0;
                *(uint32_t*)(Ch + (size_t)r1 * 512 + cb) = ph1;
                *(uint32_t*)(Cl + (size_t)r1 * 512 + cb) = pl1;
            }
        }
    }

    if (rowsum) {
        #pragma unroll
        for (int mt = 0; mt < 4; mt++) {
            float s0 = rsum0[mt], s1 = rsum1[mt];
            s0 += __shfl_xor_sync(0xffffffffu, s0, 1);
            s0 += __shfl_xor_sync(0xffffffffu, s0, 2);
            s1 += __shfl_xor_sync(0xffffffffu, s1, 1);
            s1 += __shfl_xor_sync(0xffffffffu, s1, 2);
            if ((lane & 3) == 0) {
                const int r0 = m0 + wm + mt * 16 + (lane >> 2);
                atomicAdd(rowsum + r0, s0);
                atomicAdd(rowsum + r0 + 8, s1);
            }
        }
    }
    if (doMinMax) {
        #pragma unroll
        for (int o = 16; o; o >>= 1) {
            vmn = fminf(vmn, __shfl_xor_sync(0xffffffffu, vmn, o));
            vmx = fmaxf(vmx, __shfl_xor_sync(0xffffffffu, vmx, o));
        }
        if (lane == 0) { s_mn[wid] = vmn; s_mx[wid] = vmx; }
        __syncthreads();
        if (tid == 0) {
            float bmn = s_mn[0], bmx = s_mx[0];
            #pragma unroll
            for (int w = 1; w < 8; w++) { bmn = fminf(bmn, s_mn[w]); bmx = fmaxf(bmx, s_mx[w]); }
            atomicMin(&g_minmax[0], fenc(bmn));
            atomicMax(&g_minmax[1], fenc(bmx));
        }
    }
}

// ---------------- post-row: iso + frac from accumulated row sums ----------------
__global__ void postrow_kernel(float* __restrict__ iso, float* __restrict__ frac, int B) {
    int t = blockIdx.x * blockDim.x + threadIdx.x;
    if (t >= B) return;
    float me = g_rs_esc[t] * (1.0f / 512.0f);
    iso[t] = (me > 0.5f) ? 1.0f : 0.0f;
    float mb = g_rs_bnd[t] * (1.0f / 512.0f);
    frac[t] = 1.0f / (1.0f + expf(-mb));
}

// ---------------- histogram ----------------
__global__ void hist_kernel(const float* __restrict__ bnd, int n4) {
    __shared__ unsigned sh[256 * 32];
    for (int t = threadIdx.x; t < 256 * 32; t += blockDim.x) sh[t] = 0u;
    __syncthreads();

    float mn = fdec(g_minmax[0]);
    float mx = fdec(g_minmax[1]);
    float scale = 256.0f / (mx - mn);
    int lane = threadIdx.x & 31;

    const float4* p = (const float4*)bnd;
    for (int idx = blockIdx.x * blockDim.x + threadIdx.x; idx < n4;
         idx += gridDim.x * blockDim.x) {
        float4 v = p[idx];
        int b0 = min(255, max(0, (int)((v.x - mn) * scale)));
        int b1 = min(255, max(0, (int)((v.y - mn) * scale)));
        int b2 = min(255, max(0, (int)((v.z - mn) * scale)));
        int b3 = min(255, max(0, (int)((v.w - mn) * scale)));
        atomicAdd(&sh[b0 * 32 + lane], 1u);
        atomicAdd(&sh[b1 * 32 + lane], 1u);
        atomicAdd(&sh[b2 * 32 + lane], 1u);
        atomicAdd(&sh[b3 * 32 + lane], 1u);
    }
    __syncthreads();
    for (int t = threadIdx.x; t < 256; t += blockDim.x) {
        unsigned sum = 0;
        #pragma unroll
        for (int l = 0; l < 32; l++) sum += sh[t * 32 + l];
        if (sum) atomicAdd(&g_hist[t], sum);
    }
}

// ---------------- entropy ----------------
__global__ void finalize_kernel(float* __restrict__ comp, float total) {
    __shared__ float sh[256];
    int t = threadIdx.x;
    float p = (float)g_hist[t] / total;
    sh[t] = p * log2f(p + 1e-10f);
    __syncthreads();
    for (int s = 128; s; s >>= 1) {
        if (t < s) sh[t] += sh[t + s];
        __syncthreads();
    }
    if (t == 0) comp[0] = -sh[0];
}

// ---------------- launch ----------------
extern "C" void kernel_launch(void* const* d_in, const int* in_sizes, int n_in,
                              void* d_out, int out_size) {
    const float* pts = (const float*)d_in[0];
    const float* We1 = (const float*)d_in[1];
    const float* be1 = (const float*)d_in[2];
    const float* We2 = (const float*)d_in[3];
    const float* be2 = (const float*)d_in[4];
    const float* Wo1 = (const float*)d_in[5];
    const float* bo1 = (const float*)d_in[6];
    const float* Wo2 = (const float*)d_in[7];
    const float* bo2 = (const float*)d_in[8];
    const float* Wb1 = (const float*)d_in[9];
    const float* bb1 = (const float*)d_in[10];
    const float* Wb2 = (const float*)d_in[11];
    const float* bb2 = (const float*)d_in[12];

    const int B = in_sizes[0] / 2;

    float* out  = (float*)d_out;
    float* out0 = out;
    float* out1 = out0 + (size_t)B * DIM;
    float* out2 = out1 + (size_t)B * DIM;
    float* iso  = out2 + (size_t)B * DIM;
    float* frac = iso + B;
    float* comp = frac + B;

    static __nv_bfloat16 *peh=nullptr,*pel,*poh,*pol,*pbh,*pbl;
    static __nv_bfloat16 *w0h,*w0l,*w1h,*w1l,*w2h,*w2l,*w3h,*w3l;
    static float *prse, *prsb;
    if (!peh) {
        cudaGetSymbolAddress((void**)&peh, g_h1e_h);
        cudaGetSymbolAddress((void**)&pel, g_h1e_l);
        cudaGetSymbolAddress((void**)&poh, g_h1o_h);
        cudaGetSymbolAddress((void**)&pol, g_h1o_l);
        cudaGetSymbolAddress((void**)&pbh, g_hb_h);
        cudaGetSymbolAddress((void**)&pbl, g_hb_l);
        cudaGetSymbolAddress((void**)&w0h, g_W0h);
        cudaGetSymbolAddress((void**)&w0l, g_W0l);
        cudaGetSymbolAddress((void**)&w1h, g_W1h);
        cudaGetSymbolAddress((void**)&w1l, g_W1l);
        cudaGetSymbolAddress((void**)&w2h, g_W2h);
        cudaGetSymbolAddress((void**)&w2l, g_W2l);
        cudaGetSymbolAddress((void**)&w3h, g_W3h);
        cudaGetSymbolAddress((void**)&w3l, g_W3l);
        cudaGetSymbolAddress((void**)&prse, g_rs_esc);
        cudaGetSymbolAddress((void**)&prsb, g_rs_bnd);
        cudaFuncSetAttribute(tgemm_kernel, cudaFuncAttributeMaxDynamicSharedMemorySize, TG_SMEM);
    }

    init_kernel<<<MAXB / 256, 256>>>();
    mandel_kernel<<<(B + 255) / 256, 256>>>(pts, B);
    layer1_kernel<<<(B * DIM) / 256, 256>>>(We1, be1, Wo1, bo1, B);
    prepw_all_kernel<<<(2560 * 512) / 256, 256>>>(We2, Wo2, Wb1, Wb2);

    dim3 gg(4, B / 128);
    // gemm1: escape_field = h1e @ We2 + be2  (fp32 out + fused row sums)
    tgemm_kernel<<<gg, 256, TG_SMEM>>>(peh, pel, peh, pel, nullptr, nullptr, 0,
                                       w0h, w0l, be2, out0, nullptr, nullptr,
                                       prse, 0, 512, 0);
    // gemm2: orbit_field = h1o @ Wo2 + bo2
    tgemm_kernel<<<gg, 256, TG_SMEM>>>(poh, pol, poh, pol, nullptr, nullptr, 0,
                                       w1h, w1l, bo2, out1, nullptr, nullptr,
                                       nullptr, 0, 512, 0);
    // gemm3: h1b = tanh([escape|orbit] @ Wb1 + bb1)  (fp32 A, bf16 split out)
    tgemm_kernel<<<gg, 256, TG_SMEM>>>(nullptr, nullptr, nullptr, nullptr, out0, out1, 1,
                                       w2h, w2l, bb1, nullptr, pbh, pbl,
                                       nullptr, 0, 1024, 1);
    // gemm4: boundary_field = h1b @ Wb2 + bb2  (fp32 out + fused row sums + min/max)
    tgemm_kernel<<<gg, 256, TG_SMEM>>>(pbh, pbl, pbh, pbl, nullptr, nullptr, 0,
                                       w3h, w3l, bb2, out2, nullptr, nullptr,
                                       prsb, 1, 512, 0);

    postrow_kernel<<<(B + 255) / 256, 256>>>(iso, frac, B);
    hist_kernel<<<1024, 256>>>(out2, (B * DIM) / 4);
    finalize_kernel<<<1, 256>>>(comp, (float)((size_t)B * DIM));
}